// round 1
// baseline (speedup 1.0000x reference)
#include <cuda_runtime.h>

#define NMAX 50000
#define EMAX 800000

// Scratch (device globals -- no allocation allowed in kernel_launch)
__device__ float g_agg[NMAX * 64];
__device__ float g_hA[NMAX * 64];
__device__ float g_hB[NMAX * 64];
__device__ float g_invdeg[NMAX];
__device__ int   g_deg[NMAX];

__global__ void k_zero_deg(int n) {
    int i = blockIdx.x * blockDim.x + threadIdx.x;
    if (i < n) g_deg[i] = 0;
}

__global__ void k_count(const int* __restrict__ ei, int e) {
    int i = blockIdx.x * blockDim.x + threadIdx.x;
    if (i < e) atomicAdd(&g_deg[ei[e + i]], 1);   // second row of edge_index = dst
}

__global__ void k_invdeg(int n) {
    int i = blockIdx.x * blockDim.x + threadIdx.x;
    if (i < n) g_invdeg[i] = 1.0f / fmaxf((float)g_deg[i], 1.0f);
}

__global__ void k_zero_agg(int n4) {
    int i = blockIdx.x * blockDim.x + threadIdx.x;
    if (i < n4) ((float4*)g_agg)[i] = make_float4(0.f, 0.f, 0.f, 0.f);
}

// One edge per 16 threads; each thread moves one float4 (16B) and issues one
// vector reduction (red.global.add.v4.f32, sm_90+).
__global__ void k_scatter(const float* __restrict__ h, const int* __restrict__ ei, int e) {
    int t = blockIdx.x * blockDim.x + threadIdx.x;
    int edge = t >> 4;
    if (edge >= e) return;
    int j = (t & 15) * 4;
    int s = ei[edge];       // src
    int d = ei[e + edge];   // dst
    float4 v = *(const float4*)(h + (size_t)s * 64 + j);
    float* p = g_agg + (size_t)d * 64 + j;
    asm volatile("red.global.add.v4.f32 [%0], {%1,%2,%3,%4};"
                 :: "l"(p), "f"(v.x), "f"(v.y), "f"(v.z), "f"(v.w)
                 : "memory");
}

// Fused SAGE transform: out = leaky( [agg*invdeg | h] @ [Wl; Wr] + bl )
// A tile: 32 rows x 128 cols staged in shared. B: 128x64 in shared.
// 128 threads, each computes a 4x4 output tile. 48KB static smem exactly.
__global__ void __launch_bounds__(128) k_transform(
    const float* __restrict__ h,
    const float* __restrict__ Wl, const float* __restrict__ bl,
    const float* __restrict__ Wr,
    float* __restrict__ out, int n)
{
    __shared__ float Bs[128 * 64];   // B[k][c], k<64 -> Wl, k>=64 -> Wr
    __shared__ float As[32 * 128];   // A[r][k]
    const int tid = threadIdx.x;

    // Load weights into shared (8192 floats = 2048 float4; 16 per thread)
    {
        const float4* wl4 = (const float4*)Wl;
        const float4* wr4 = (const float4*)Wr;
        float4* bs4 = (float4*)Bs;
        #pragma unroll
        for (int i = 0; i < 8; i++) {
            bs4[i * 128 + tid]        = wl4[i * 128 + tid];
            bs4[1024 + i * 128 + tid] = wr4[i * 128 + tid];
        }
    }

    const int row0 = blockIdx.x * 32;
    // Stage A tile: per row, cols [0,64) = agg*invdeg, cols [64,128) = h
    {
        float4* as4 = (float4*)As;
        #pragma unroll
        for (int ii = 0; ii < 8; ii++) {
            int i = ii * 128 + tid;     // float4 index into 32x128 tile
            int r = i >> 5;             // 32 float4s per row
            int q = i & 31;
            int gr = row0 + r;
            float4 v = make_float4(0.f, 0.f, 0.f, 0.f);
            if (gr < n) {
                if (q < 16) {
                    v = *(const float4*)(g_agg + (size_t)gr * 64 + q * 4);
                    float sc = g_invdeg[gr];
                    v.x *= sc; v.y *= sc; v.z *= sc; v.w *= sc;
                } else {
                    v = *(const float4*)(h + (size_t)gr * 64 + (q - 16) * 4);
                }
            }
            as4[i] = v;
        }
    }
    __syncthreads();

    const int rg = tid >> 4;   // 0..7 (row group)
    const int cg = tid & 15;   // 0..15 (col group)
    float acc[4][4];
    #pragma unroll
    for (int i = 0; i < 4; i++)
        #pragma unroll
        for (int j = 0; j < 4; j++) acc[i][j] = 0.f;

    const float* a0 = As + (rg * 4) * 128;
    #pragma unroll 16
    for (int k = 0; k < 128; k++) {
        float4 b = *(const float4*)(Bs + k * 64 + cg * 4);
        float av[4];
        #pragma unroll
        for (int i = 0; i < 4; i++) av[i] = a0[i * 128 + k];
        #pragma unroll
        for (int i = 0; i < 4; i++) {
            acc[i][0] += av[i] * b.x;
            acc[i][1] += av[i] * b.y;
            acc[i][2] += av[i] * b.z;
            acc[i][3] += av[i] * b.w;
        }
    }

    float4 bias = *(const float4*)(bl + cg * 4);
    #pragma unroll
    for (int i = 0; i < 4; i++) {
        int gr = row0 + rg * 4 + i;
        if (gr < n) {
            float4 o;
            o.x = acc[i][0] + bias.x;
            o.y = acc[i][1] + bias.y;
            o.z = acc[i][2] + bias.z;
            o.w = acc[i][3] + bias.w;
            o.x = o.x > 0.f ? o.x : 0.01f * o.x;
            o.y = o.y > 0.f ? o.y : 0.01f * o.y;
            o.z = o.z > 0.f ? o.z : 0.01f * o.z;
            o.w = o.w > 0.f ? o.w : 0.01f * o.w;
            *(float4*)(out + (size_t)gr * 64 + cg * 4) = o;
        }
    }
}

// Head: out[i] = h[i,:] . W_out + b_out    (warp per row)
__global__ void k_out(const float* __restrict__ h, const float* __restrict__ Wo,
                      const float* __restrict__ bo, float* __restrict__ out, int n)
{
    int gtid = blockIdx.x * blockDim.x + threadIdx.x;
    int row  = gtid >> 5;
    int lane = gtid & 31;
    if (row >= n) return;
    float2 hv = *(const float2*)(h + (size_t)row * 64 + lane * 2);
    float2 wv = *(const float2*)(Wo + lane * 2);
    float s = hv.x * wv.x + hv.y * wv.y;
    #pragma unroll
    for (int o = 16; o; o >>= 1) s += __shfl_xor_sync(0xffffffffu, s, o);
    if (lane == 0) out[row] = s + bo[0];
}

extern "C" void kernel_launch(void* const* d_in, const int* in_sizes, int n_in,
                              void* d_out, int out_size)
{
    const float* x   = (const float*)d_in[0];
    const int*   ei  = (const int*)d_in[1];
    const float* Wl1 = (const float*)d_in[2];
    const float* bl1 = (const float*)d_in[3];
    const float* Wr1 = (const float*)d_in[4];
    const float* Wl2 = (const float*)d_in[5];
    const float* bl2 = (const float*)d_in[6];
    const float* Wr2 = (const float*)d_in[7];
    const float* Wl3 = (const float*)d_in[8];
    const float* bl3 = (const float*)d_in[9];
    const float* Wr3 = (const float*)d_in[10];
    const float* Wo  = (const float*)d_in[11];
    const float* bo  = (const float*)d_in[12];
    float* out = (float*)d_out;

    const int n = in_sizes[0] / 64;
    const int e = in_sizes[1] / 2;

    float *hA = nullptr, *hB = nullptr;
    cudaGetSymbolAddress((void**)&hA, g_hA);
    cudaGetSymbolAddress((void**)&hB, g_hB);

    const int nb  = (n + 255) / 256;
    const int eb  = (e + 255) / 256;
    const int zb  = (n * 16 + 255) / 256;       // zero agg (float4 granularity)
    const int sb  = (e * 16 + 255) / 256;       // scatter: 16 threads/edge
    const int tb  = (n + 31) / 32;              // transform: 32 rows/block

    // degree + inverse degree
    k_zero_deg<<<nb, 256>>>(n);
    k_count<<<eb, 256>>>(ei, e);
    k_invdeg<<<nb, 256>>>(n);

    // layer 1: x -> hA
    k_zero_agg<<<zb, 256>>>(n * 16);
    k_scatter<<<sb, 256>>>(x, ei, e);
    k_transform<<<tb, 128>>>(x, Wl1, bl1, Wr1, hA, n);

    // layer 2: hA -> hB
    k_zero_agg<<<zb, 256>>>(n * 16);
    k_scatter<<<sb, 256>>>(hA, ei, e);
    k_transform<<<tb, 128>>>(hA, Wl2, bl2, Wr2, hB, n);

    // layer 3: hB -> hA
    k_zero_agg<<<zb, 256>>>(n * 16);
    k_scatter<<<sb, 256>>>(hB, ei, e);
    k_transform<<<tb, 128>>>(hB, Wl3, bl3, Wr3, hA, n);

    // head
    k_out<<<(n * 32 + 255) / 256, 256>>>(hA, Wo, bo, out, n);
}

// round 2
// speedup vs baseline: 1.2074x; 1.2074x over previous
#include <cuda_runtime.h>

#define NMAX 50000
#define EMAX 800000

// Scratch (device globals -- no allocation allowed in kernel_launch)
__device__ float g_agg[NMAX * 64];
__device__ float g_hA[NMAX * 64];
__device__ float g_hB[NMAX * 64];
__device__ int   g_deg[NMAX];
__device__ int   g_off[NMAX + 1];
__device__ int   g_cur[NMAX];
__device__ int   g_csr[EMAX];
__device__ int   g_bsum[128];
__device__ int   g_bsumex[128];

// ---------------- CSR build ----------------

__global__ void k_zero_deg(int n) {
    int i = blockIdx.x * blockDim.x + threadIdx.x;
    if (i < n) g_deg[i] = 0;
}

__global__ void k_count(const int* __restrict__ ei, int e) {
    int i = blockIdx.x * blockDim.x + threadIdx.x;
    if (i < e) atomicAdd(&g_deg[ei[e + i]], 1);   // row 1 of edge_index = dst
}

// per-1024-node block sums of degree
__global__ void k_blocksum(int n) {
    __shared__ int sm[256];
    int t = threadIdx.x, b = blockIdx.x;
    int base = b * 1024 + t * 4;
    int s = 0;
    #pragma unroll
    for (int u = 0; u < 4; u++) { int i = base + u; if (i < n) s += g_deg[i]; }
    sm[t] = s; __syncthreads();
    #pragma unroll
    for (int o = 128; o; o >>= 1) { if (t < o) sm[t] += sm[t + o]; __syncthreads(); }
    if (t == 0) g_bsum[b] = sm[0];
}

// exclusive scan of block sums (<=128 blocks), single block
__global__ void k_scanbsum(int nbs, int e, int n) {
    __shared__ int sm[128];
    int t = threadIdx.x;
    sm[t] = (t < nbs) ? g_bsum[t] : 0;
    __syncthreads();
    #pragma unroll
    for (int o = 1; o < 128; o <<= 1) {
        int v = (t >= o) ? sm[t - o] : 0;
        __syncthreads();
        sm[t] += v;
        __syncthreads();
    }
    int excl = (t == 0) ? 0 : sm[t - 1];
    if (t < nbs) g_bsumex[t] = excl;
    if (t == 0) g_off[n] = e;
}

// per-node exclusive offsets
__global__ void k_offsets(int n) {
    __shared__ int sm[256];
    int t = threadIdx.x, b = blockIdx.x;
    int base = b * 1024 + t * 4;
    int v[4]; int s = 0;
    #pragma unroll
    for (int u = 0; u < 4; u++) { v[u] = (base + u < n) ? g_deg[base + u] : 0; s += v[u]; }
    sm[t] = s; __syncthreads();
    #pragma unroll
    for (int o = 1; o < 256; o <<= 1) {
        int val = (t >= o) ? sm[t - o] : 0;
        __syncthreads();
        sm[t] += val;
        __syncthreads();
    }
    int excl = sm[t] - s + g_bsumex[b];
    #pragma unroll
    for (int u = 0; u < 4; u++) {
        if (base + u < n) { g_off[base + u] = excl; g_cur[base + u] = excl; excl += v[u]; }
    }
}

__global__ void k_place(const int* __restrict__ ei, int e) {
    int i = blockIdx.x * blockDim.x + threadIdx.x;
    if (i >= e) return;
    int s = ei[i];
    int d = ei[e + i];
    int pos = atomicAdd(&g_cur[d], 1);
    g_csr[pos] = s;
}

// ---------------- mean aggregation (warp per node, gather) ----------------

__global__ void k_aggregate(const float* __restrict__ h, int n) {
    int warp = (blockIdx.x * blockDim.x + threadIdx.x) >> 5;
    int lane = threadIdx.x & 31;
    if (warp >= n) return;
    int beg = g_off[warp];
    int end = g_off[warp + 1];

    float2 a0 = make_float2(0.f, 0.f), a1 = a0, a2 = a0, a3 = a0;
    int j = beg;
    for (; j + 3 < end; j += 4) {
        int s0 = __ldg(&g_csr[j]);
        int s1 = __ldg(&g_csr[j + 1]);
        int s2 = __ldg(&g_csr[j + 2]);
        int s3 = __ldg(&g_csr[j + 3]);
        float2 v0 = *(const float2*)(h + (size_t)s0 * 64 + lane * 2);
        float2 v1 = *(const float2*)(h + (size_t)s1 * 64 + lane * 2);
        float2 v2 = *(const float2*)(h + (size_t)s2 * 64 + lane * 2);
        float2 v3 = *(const float2*)(h + (size_t)s3 * 64 + lane * 2);
        a0.x += v0.x; a0.y += v0.y;
        a1.x += v1.x; a1.y += v1.y;
        a2.x += v2.x; a2.y += v2.y;
        a3.x += v3.x; a3.y += v3.y;
    }
    for (; j < end; j++) {
        int s = __ldg(&g_csr[j]);
        float2 v = *(const float2*)(h + (size_t)s * 64 + lane * 2);
        a0.x += v.x; a0.y += v.y;
    }
    float inv = 1.0f / fmaxf((float)(end - beg), 1.0f);
    float2 r;
    r.x = (a0.x + a1.x + a2.x + a3.x) * inv;
    r.y = (a0.y + a1.y + a2.y + a3.y) * inv;
    *(float2*)(g_agg + (size_t)warp * 64 + lane * 2) = r;
}

// ---------------- fused SAGE transform with packed f32x2 FMA ----------------
// out = leaky( [mean_nb | h] @ [Wl; Wr] + bl ),  A: 32x128 tile, B: 128x64.
// 64 threads: thread tile = 8 rows x 4 cols. 48KB static smem.

__device__ __forceinline__ unsigned long long pack2(float a) {
    unsigned long long r;
    asm("mov.b64 %0, {%1, %1};" : "=l"(r) : "f"(a));
    return r;
}
__device__ __forceinline__ unsigned long long fma2(unsigned long long a,
                                                   unsigned long long b,
                                                   unsigned long long c) {
    unsigned long long d;
    asm("fma.rn.f32x2 %0, %1, %2, %3;" : "=l"(d) : "l"(a), "l"(b), "l"(c));
    return d;
}

__global__ void __launch_bounds__(64) k_transform(
    const float* __restrict__ h,
    const float* __restrict__ Wl, const float* __restrict__ bl,
    const float* __restrict__ Wr,
    float* __restrict__ out, int n)
{
    __shared__ float Bs[128 * 64];   // B[k][c]: k<64 -> Wl, k>=64 -> Wr
    __shared__ float As[32 * 128];   // A[r][k]: k<64 -> mean_nb, k>=64 -> h
    const int tid = threadIdx.x;

    // stage weights: 2048 float4, 32 per thread
    {
        const float4* wl4 = (const float4*)Wl;
        const float4* wr4 = (const float4*)Wr;
        float4* bs4 = (float4*)Bs;
        #pragma unroll
        for (int i = 0; i < 16; i++) {
            bs4[i * 64 + tid]        = wl4[i * 64 + tid];
            bs4[1024 + i * 64 + tid] = wr4[i * 64 + tid];
        }
    }

    const int row0 = blockIdx.x * 32;
    // stage A tile: 1024 float4, 16 per thread
    {
        float4* as4 = (float4*)As;
        #pragma unroll
        for (int ii = 0; ii < 16; ii++) {
            int i = ii * 64 + tid;
            int r = i >> 5;           // 32 float4 per row
            int q = i & 31;
            int gr = row0 + r;
            float4 v = make_float4(0.f, 0.f, 0.f, 0.f);
            if (gr < n) {
                if (q < 16) v = *(const float4*)(g_agg + (size_t)gr * 64 + q * 4);
                else        v = *(const float4*)(h + (size_t)gr * 64 + (q - 16) * 4);
            }
            as4[i] = v;
        }
    }
    __syncthreads();

    const int rg = tid >> 4;   // 0..3 -> rows rg*8 .. rg*8+7
    const int cg = tid & 15;   // 0..15 -> cols cg*4 .. cg*4+3

    unsigned long long acc0[8], acc1[8];
    #pragma unroll
    for (int i = 0; i < 8; i++) { acc0[i] = 0ull; acc1[i] = 0ull; }

    const unsigned asA = (unsigned)__cvta_generic_to_shared(As + (rg * 8) * 128);
    const unsigned asB = (unsigned)__cvta_generic_to_shared(Bs + cg * 4);

    #pragma unroll 4
    for (int k = 0; k < 128; k++) {
        unsigned long long b01, b23;
        asm("ld.shared.v2.u64 {%0, %1}, [%2];"
            : "=l"(b01), "=l"(b23) : "r"(asB + k * 256));
        #pragma unroll
        for (int i = 0; i < 8; i++) {
            float a;
            asm("ld.shared.f32 %0, [%1];" : "=f"(a) : "r"(asA + (i * 128 + k) * 4));
            unsigned long long aa = pack2(a);
            acc0[i] = fma2(aa, b01, acc0[i]);
            acc1[i] = fma2(aa, b23, acc1[i]);
        }
    }

    float4 bias = *(const float4*)(bl + cg * 4);
    #pragma unroll
    for (int i = 0; i < 8; i++) {
        int gr = row0 + rg * 8 + i;
        if (gr < n) {
            float4 o;
            asm("mov.b64 {%0, %1}, %2;" : "=f"(o.x), "=f"(o.y) : "l"(acc0[i]));
            asm("mov.b64 {%0, %1}, %2;" : "=f"(o.z), "=f"(o.w) : "l"(acc1[i]));
            o.x += bias.x; o.y += bias.y; o.z += bias.z; o.w += bias.w;
            o.x = o.x > 0.f ? o.x : 0.01f * o.x;
            o.y = o.y > 0.f ? o.y : 0.01f * o.y;
            o.z = o.z > 0.f ? o.z : 0.01f * o.z;
            o.w = o.w > 0.f ? o.w : 0.01f * o.w;
            *(float4*)(out + (size_t)gr * 64 + cg * 4) = o;
        }
    }
}

// ---------------- output head ----------------

__global__ void k_out(const float* __restrict__ h, const float* __restrict__ Wo,
                      const float* __restrict__ bo, float* __restrict__ out, int n)
{
    int gtid = blockIdx.x * blockDim.x + threadIdx.x;
    int row  = gtid >> 5;
    int lane = gtid & 31;
    if (row >= n) return;
    float2 hv = *(const float2*)(h + (size_t)row * 64 + lane * 2);
    float2 wv = *(const float2*)(Wo + lane * 2);
    float s = hv.x * wv.x + hv.y * wv.y;
    #pragma unroll
    for (int o = 16; o; o >>= 1) s += __shfl_xor_sync(0xffffffffu, s, o);
    if (lane == 0) out[row] = s + bo[0];
}

extern "C" void kernel_launch(void* const* d_in, const int* in_sizes, int n_in,
                              void* d_out, int out_size)
{
    const float* x   = (const float*)d_in[0];
    const int*   ei  = (const int*)d_in[1];
    const float* Wl1 = (const float*)d_in[2];
    const float* bl1 = (const float*)d_in[3];
    const float* Wr1 = (const float*)d_in[4];
    const float* Wl2 = (const float*)d_in[5];
    const float* bl2 = (const float*)d_in[6];
    const float* Wr2 = (const float*)d_in[7];
    const float* Wl3 = (const float*)d_in[8];
    const float* bl3 = (const float*)d_in[9];
    const float* Wr3 = (const float*)d_in[10];
    const float* Wo  = (const float*)d_in[11];
    const float* bo  = (const float*)d_in[12];
    float* out = (float*)d_out;

    const int n = in_sizes[0] / 64;
    const int e = in_sizes[1] / 2;

    float *hA = nullptr, *hB = nullptr;
    cudaGetSymbolAddress((void**)&hA, g_hA);
    cudaGetSymbolAddress((void**)&hB, g_hB);

    const int nb  = (n + 255) / 256;
    const int eb  = (e + 255) / 256;
    const int nbs = (n + 1023) / 1024;
    const int ab  = (n * 32 + 255) / 256;   // aggregate: warp per node
    const int tb  = (n + 31) / 32;          // transform: 32 rows per block

    // CSR build (by destination)
    k_zero_deg<<<nb, 256>>>(n);
    k_count<<<eb, 256>>>(ei, e);
    k_blocksum<<<nbs, 256>>>(n);
    k_scanbsum<<<1, 128>>>(nbs, e, n);
    k_offsets<<<nbs, 256>>>(n);
    k_place<<<eb, 256>>>(ei, e);

    // layer 1: x -> hA
    k_aggregate<<<ab, 256>>>(x, n);
    k_transform<<<tb, 64>>>(x, Wl1, bl1, Wr1, hA, n);

    // layer 2: hA -> hB
    k_aggregate<<<ab, 256>>>(hA, n);
    k_transform<<<tb, 64>>>(hA, Wl2, bl2, Wr2, hB, n);

    // layer 3: hB -> hA
    k_aggregate<<<ab, 256>>>(hB, n);
    k_transform<<<tb, 64>>>(hB, Wl3, bl3, Wr3, hA, n);

    // head
    k_out<<<(n * 32 + 255) / 256, 256>>>(hA, Wo, bo, out, n);
}